// round 15
// baseline (speedup 1.0000x reference)
#include <cuda_runtime.h>
#include <cuda_fp16.h>
#include <cstdint>

// ---------------- problem dims ----------------
#define T_TOKENS 8192
#define DIM      1024
#define FF       2048
#define NEXP     8
#define RH       128
#define NSLOTS   (T_TOKENS * 2)
#define KSPLIT   4

// ---------------- device scratch ----------------
__device__ __half g_xh[(long long)T_TOKENS * DIM];
__device__ __half g_h[(long long)NSLOTS * FF];
__device__ __half g_w1t[(long long)NEXP * FF * DIM];        // W1^T [e][f][d]
__device__ __half g_w2t[(long long)NEXP * DIM * FF];        // W2^T [e][d][f]
__device__ float  g_rpart[(long long)KSPLIT * T_TOKENS * RH];
__device__ int    g_tok[NEXP * T_TOKENS];
__device__ int    g_slot[NEXP * T_TOKENS];
__device__ int    g_cnt[NEXP];
__device__ int    g_off[NEXP];
__device__ int    g_rt[NEXP + 1];        // cumulative row-tiles per expert
__device__ int    g_ctr[2];              // persistent tile counters
__device__ int    g_ptok[NSLOTS];
__device__ float  g_pw[NSLOTS];
__device__ float  g_rw[NSLOTS];

// ---------------- helpers ----------------
__device__ __forceinline__ uint32_t cvta_s(const void* p) {
    uint32_t a;
    asm("{ .reg .u64 t; cvta.to.shared.u64 t, %1; cvt.u32.u64 %0, t; }" : "=r"(a) : "l"(p));
    return a;
}
__device__ __forceinline__ void cp16(uint32_t s, const void* g) {
    asm volatile("cp.async.cg.shared.global [%0], [%1], 16;" :: "r"(s), "l"(g));
}
__device__ __forceinline__ float silu_f(float v) { return v / (1.0f + __expf(-v)); }

__device__ __forceinline__ void mma16816(float* c, const uint32_t* a, const uint32_t* b) {
    asm volatile(
        "mma.sync.aligned.m16n8k16.row.col.f32.f16.f16.f32 "
        "{%0,%1,%2,%3}, {%4,%5,%6,%7}, {%8,%9}, {%0,%1,%2,%3};"
        : "+f"(c[0]), "+f"(c[1]), "+f"(c[2]), "+f"(c[3])
        : "r"(a[0]), "r"(a[1]), "r"(a[2]), "r"(a[3]), "r"(b[0]), "r"(b[1]));
}

__device__ __forceinline__ void splitpair(float x, float y, uint32_t& hi, uint32_t& lo) {
    const __half2 h = __floats2half2_rn(x, y);
    const float2 hf = __half22float2(h);
    const __half2 l = __floats2half2_rn(x - hf.x, y - hf.y);
    hi = *(const uint32_t*)&h;
    lo = *(const uint32_t*)&l;
}

// ================ persistent fp16 grouped GEMM (m16n8k16) ================
// MODE 0: A gathered via ptok from g_xh; silu -> half out (perm rows). NT=16.
// MODE 1: A direct (perm order); weighted atomicAdd into out[token]. NT=8.
#define HSTAGES 4
#define ASTR_H  40
#define A_HALFS (128 * ASTR_H)
#define B_HALFS (128 * ASTR_H)
#define SFH     (A_HALFS + B_HALFS)
#define SBYT_H  (SFH * 2)

template <int MODE>
__global__ __launch_bounds__(256, 2)
void hgemm(const __half* __restrict__ A, const __half* __restrict__ Bt,
           __half* __restrict__ Ch, float* __restrict__ Cf,
           int N, int K,
           const int* __restrict__ cnt, const int* __restrict__ off,
           const int* __restrict__ ptok, const float* __restrict__ pw)
{
    extern __shared__ __half smh[];
    __shared__ int s_tile;

    const int tid = threadIdx.x;
    const uint32_t sbase = cvta_s(smh);
    const int wid = tid >> 5, lane = tid & 31;
    const int wm = (wid & 3) * 32, wn = (wid >> 2) * 64;
    const int l4 = lane >> 2, lq = lane & 3;

    // cache cumulative row-tile table + totals
    int rt_cum[NEXP + 1];
#pragma unroll
    for (int i = 0; i <= NEXP; i++) rt_cum[i] = g_rt[i];
    const int NT = (MODE == 0) ? (FF / 128) : (DIM / 128);
    const int total = rt_cum[NEXP] * NT;

    for (;;) {
        if (tid == 0) s_tile = atomicAdd(&g_ctr[MODE], 1);
        __syncthreads();
        const int tile = s_tile;
        __syncthreads();
        if (tile >= total) break;

        // decode tile -> (e, row-tile, n-tile)
        const int rt = (MODE == 0) ? (tile >> 4) : (tile >> 3);
        const int tx = (MODE == 0) ? (tile & 15) : (tile & 7);
        int e = 0;
#pragma unroll
        for (int k = 1; k < NEXP; k++) if (rt >= rt_cum[k]) e = k;
        const int row0 = off[e] + (rt - rt_cum[e]) * 128;
        const int mend = off[e] + cnt[e];
        const int n0 = tx * 128;
        const __half* Bp = Bt + (long long)e * N * K;

        // per-tile loader descriptors
        const __half* aSrc[2]; uint32_t aDst[2];
        const __half* bSrc[2]; uint32_t bDst[2];
#pragma unroll
        for (int i = 0; i < 2; i++) {
            const int idx = tid + i * 256;
            const int ar = idx >> 2, ac = idx & 3;
            int prow = row0 + ar;
            if (prow > mend - 1) prow = mend - 1;
            const long long arow = (MODE == 0) ? (long long)ptok[prow] : (long long)prow;
            aSrc[i] = A + arow * K + ac * 8;
            aDst[i] = sbase + (uint32_t)(ar * 80 + ac * 16);
            bSrc[i] = Bp + (long long)(n0 + ar) * K + ac * 8;
            bDst[i] = sbase + (uint32_t)(A_HALFS * 2 + ar * 80 + ac * 16);
        }

        const int nk = K / 32;
#pragma unroll
        for (int s = 0; s < 3; s++) {
#pragma unroll
            for (int i = 0; i < 2; i++) {
                cp16(aDst[i] + s * SBYT_H, aSrc[i] + s * 32);
                cp16(bDst[i] + s * SBYT_H, bSrc[i] + s * 32);
            }
            asm volatile("cp.async.commit_group;" ::: "memory");
        }

        float acc[2][8][4];
#pragma unroll
        for (int mt = 0; mt < 2; mt++)
#pragma unroll
            for (int nt = 0; nt < 8; nt++)
#pragma unroll
                for (int q = 0; q < 4; q++) acc[mt][nt][q] = 0.0f;

        for (int kt = 0; kt < nk; kt++) {
            asm volatile("cp.async.wait_group 2;" ::: "memory");
            __syncthreads();
            if (kt + 3 < nk) {
                const int s = (kt + 3) & 3;
#pragma unroll
                for (int i = 0; i < 2; i++) {
                    cp16(aDst[i] + s * SBYT_H, aSrc[i] + (kt + 3) * 32);
                    cp16(bDst[i] + s * SBYT_H, bSrc[i] + (kt + 3) * 32);
                }
            }
            asm volatile("cp.async.commit_group;" ::: "memory");

            const __half* st = smh + (kt & 3) * SFH;
#pragma unroll
            for (int ks = 0; ks < 2; ks++) {
                const int kk = ks * 16;
                uint32_t a[2][4], b[8][2];
#pragma unroll
                for (int mt = 0; mt < 2; mt++) {
                    const __half* ap = st + (wm + mt * 16 + l4) * ASTR_H + kk + 2 * lq;
                    a[mt][0] = *(const uint32_t*)(ap);
                    a[mt][1] = *(const uint32_t*)(ap + 8 * ASTR_H);
                    a[mt][2] = *(const uint32_t*)(ap + 8);
                    a[mt][3] = *(const uint32_t*)(ap + 8 * ASTR_H + 8);
                }
#pragma unroll
                for (int nt = 0; nt < 8; nt++) {
                    const __half* bp = st + A_HALFS + (wn + nt * 8 + l4) * ASTR_H + kk + 2 * lq;
                    b[nt][0] = *(const uint32_t*)(bp);
                    b[nt][1] = *(const uint32_t*)(bp + 8);
                }
#pragma unroll
                for (int mt = 0; mt < 2; mt++)
#pragma unroll
                    for (int nt = 0; nt < 8; nt++)
                        mma16816(acc[mt][nt], a[mt], b[nt]);
            }
        }

        // epilogue
#pragma unroll
        for (int mt = 0; mt < 2; mt++) {
#pragma unroll
            for (int hr = 0; hr < 2; hr++) {
                const int row = row0 + wm + mt * 16 + l4 + hr * 8;
                if (row < mend) {
                    if (MODE == 0) {
                        __half* cp0 = Ch + (long long)row * N + n0 + wn + lq * 2;
#pragma unroll
                        for (int nt = 0; nt < 8; nt++) {
                            const float v0 = silu_f(acc[mt][nt][hr * 2 + 0]);
                            const float v1 = silu_f(acc[mt][nt][hr * 2 + 1]);
                            *(__half2*)(cp0 + nt * 8) = __floats2half2_rn(v0, v1);
                        }
                    } else {
                        const int t = ptok[row];
                        const float w = pw[row];
                        float* cp0 = Cf + (long long)t * N + n0 + wn + lq * 2;
#pragma unroll
                        for (int nt = 0; nt < 8; nt++) {
                            atomicAdd(cp0 + nt * 8 + 0, w * acc[mt][nt][hr * 2 + 0]);
                            atomicAdd(cp0 + nt * 8 + 1, w * acc[mt][nt][hr * 2 + 1]);
                        }
                    }
                }
            }
        }
        __syncthreads();   // all warps done with smem before next tile's prologue
    }
}

// ================ router hidden: fp16x3 MMA with K-split ================
#define RSTAGES 3
#define ASTR 36
#define BSTR 136
#define AFL  (128 * ASTR)
#define BFL  (32 * BSTR)
#define SF   (AFL + BFL)
#define SBYT (SF * 4)

__global__ __launch_bounds__(256)
void router_mma(const float* __restrict__ x, const float* __restrict__ rw1,
                float* __restrict__ part)
{
    extern __shared__ float sm[];
    const int kz = blockIdx.x;
    const int row0 = blockIdx.y * 128;
    const int kbase = kz * (DIM / KSPLIT);

    const int tid = threadIdx.x;
    const uint32_t sbase = cvta_s(sm);

    const float* aSrc[4]; uint32_t aDst[4];
    const float* bSrc[4]; uint32_t bDst[4];
#pragma unroll
    for (int i = 0; i < 4; i++) {
        const int cidx = tid + i * 256;
        const int ar = cidx >> 3, ak = (cidx & 7) * 4;
        aSrc[i] = x + (long long)(row0 + ar) * DIM + kbase + ak;
        aDst[i] = sbase + (uint32_t)(ar * ASTR + ak) * 4u;
        const int bk = cidx >> 5, bn = (cidx & 31) * 4;
        bSrc[i] = rw1 + (long long)(kbase + bk) * RH + bn;
        bDst[i] = sbase + (uint32_t)(AFL + bk * BSTR + bn) * 4u;
    }

    const int nk = (DIM / KSPLIT) / 32;
#pragma unroll
    for (int s = 0; s < 2; s++) {
#pragma unroll
        for (int i = 0; i < 4; i++) {
            cp16(aDst[i] + s * SBYT, aSrc[i] + s * 32);
            cp16(bDst[i] + s * SBYT, bSrc[i] + (long long)s * 32 * RH);
        }
        asm volatile("cp.async.commit_group;" ::: "memory");
    }

    const int wid = tid >> 5, lane = tid & 31;
    const int wm = (wid & 3) * 32, wn = (wid >> 2) * 64;
    const int l4 = lane >> 2, lq = lane & 3;

    float acc[2][8][4];
#pragma unroll
    for (int mt = 0; mt < 2; mt++)
#pragma unroll
        for (int nt = 0; nt < 8; nt++)
#pragma unroll
            for (int q = 0; q < 4; q++) acc[mt][nt][q] = 0.0f;

    int rstage = 0, pstage = 2;
    for (int kt = 0; kt < nk; kt++) {
        asm volatile("cp.async.wait_group 1;" ::: "memory");
        __syncthreads();
        if (kt + 2 < nk) {
#pragma unroll
            for (int i = 0; i < 4; i++) {
                cp16(aDst[i] + pstage * SBYT, aSrc[i] + (kt + 2) * 32);
                cp16(bDst[i] + pstage * SBYT, bSrc[i] + (long long)(kt + 2) * 32 * RH);
            }
        }
        asm volatile("cp.async.commit_group;" ::: "memory");

        const float* st = sm + rstage * SF;
#pragma unroll
        for (int ks = 0; ks < 2; ks++) {
            const int kk = ks * 16;
            uint32_t ah[2][4], al[2][4], bh[8][2], bl[8][2];
#pragma unroll
            for (int mt = 0; mt < 2; mt++) {
                const float* ap = st + (wm + mt * 16 + l4) * ASTR + kk + 2 * lq;
                splitpair(ap[0],              ap[1],              ah[mt][0], al[mt][0]);
                splitpair(ap[8 * ASTR],       ap[8 * ASTR + 1],   ah[mt][1], al[mt][1]);
                splitpair(ap[8],              ap[9],              ah[mt][2], al[mt][2]);
                splitpair(ap[8 * ASTR + 8],   ap[8 * ASTR + 9],   ah[mt][3], al[mt][3]);
            }
#pragma unroll
            for (int nt = 0; nt < 8; nt++) {
                const float* bp = st + AFL + (kk + 2 * lq) * BSTR + wn + nt * 8 + l4;
                splitpair(bp[0],        bp[BSTR],     bh[nt][0], bl[nt][0]);
                splitpair(bp[8 * BSTR], bp[9 * BSTR], bh[nt][1], bl[nt][1]);
            }
#pragma unroll
            for (int mt = 0; mt < 2; mt++)
#pragma unroll
                for (int nt = 0; nt < 8; nt++) {
                    mma16816(acc[mt][nt], ah[mt], bh[nt]);
                    mma16816(acc[mt][nt], ah[mt], bl[nt]);
                    mma16816(acc[mt][nt], al[mt], bh[nt]);
                }
        }
        if (++rstage == RSTAGES) rstage = 0;
        if (++pstage == RSTAGES) pstage = 0;
    }

    float* base = part + (long long)kz * T_TOKENS * RH;
#pragma unroll
    for (int mt = 0; mt < 2; mt++) {
#pragma unroll
        for (int hr = 0; hr < 2; hr++) {
            const int row = row0 + wm + mt * 16 + l4 + hr * 8;
            float* cp0 = base + (long long)row * RH + wn + lq * 2;
#pragma unroll
            for (int nt = 0; nt < 8; nt++) {
                float2 v;
                v.x = acc[mt][nt][hr * 2 + 0];
                v.y = acc[mt][nt][hr * 2 + 1];
                *(float2*)(cp0 + nt * 8) = v;
            }
        }
    }
}

// ---------------- fused: KSPLIT-reduce + silu + logits + top-2 ----------------
__global__ void router_topk_kernel(const float* __restrict__ part,
                                   const float* __restrict__ w2)
{
    const int warp = (blockIdx.x * blockDim.x + threadIdx.x) >> 5;
    const int lane = threadIdx.x & 31;
    if (warp >= T_TOKENS) return;
    const long long stride = (long long)T_TOKENS * RH;
    const long long base = (long long)warp * RH;

    float acc[NEXP];
#pragma unroll
    for (int e = 0; e < NEXP; e++) acc[e] = 0.0f;
#pragma unroll
    for (int j4 = 0; j4 < RH / 32; j4++) {
        const int j = j4 * 32 + lane;
        float s = part[base + j];
#pragma unroll
        for (int kz = 1; kz < KSPLIT; kz++) s += part[base + j + kz * stride];
        s = silu_f(s);
#pragma unroll
        for (int e = 0; e < NEXP; e++) acc[e] += s * w2[j * NEXP + e];
    }
#pragma unroll
    for (int off = 16; off > 0; off >>= 1)
#pragma unroll
        for (int e = 0; e < NEXP; e++)
            acc[e] += __shfl_xor_sync(0xffffffffu, acc[e], off);
    if (lane == 0) {
        float mx = acc[0];
#pragma unroll
        for (int e = 1; e < NEXP; e++) mx = fmaxf(mx, acc[e]);
        float p[NEXP];
#pragma unroll
        for (int e = 0; e < NEXP; e++) p[e] = __expf(acc[e] - mx);
        int i0 = 0;
#pragma unroll
        for (int e = 1; e < NEXP; e++) if (p[e] > p[i0]) i0 = e;
        int i1 = (i0 == 0) ? 1 : 0;
#pragma unroll
        for (int e = 0; e < NEXP; e++) if (e != i0 && p[e] > p[i1]) i1 = e;
        const float s = p[i0] + p[i1];
        const int t = warp;
        int pos0 = atomicAdd(&g_cnt[i0], 1);
        g_tok[i0 * T_TOKENS + pos0]  = t;
        g_slot[i0 * T_TOKENS + pos0] = 2 * t;
        g_rw[2 * t] = p[i0] / s;
        int pos1 = atomicAdd(&g_cnt[i1], 1);
        g_tok[i1 * T_TOKENS + pos1]  = t;
        g_slot[i1 * T_TOKENS + pos1] = 2 * t + 1;
        g_rw[2 * t + 1] = p[i1] / s;
    }
}

// ---------------- conversions ----------------
__global__ void transpose_half_kernel(const float* __restrict__ src,
                                      __half* __restrict__ dst, int R, int C)
{
    __shared__ float tile[32][33];
    const int e = blockIdx.z;
    const float* s = src + (long long)e * R * C;
    __half* d = dst + (long long)e * R * C;
    const int c0 = blockIdx.x * 32, r0 = blockIdx.y * 32;
    const int tx = threadIdx.x, ty = threadIdx.y;
#pragma unroll
    for (int i = 0; i < 32; i += 8)
        tile[ty + i][tx] = s[(long long)(r0 + ty + i) * C + c0 + tx];
    __syncthreads();
#pragma unroll
    for (int i = 0; i < 32; i += 8)
        d[(long long)(c0 + ty + i) * R + r0 + tx] = __float2half_rn(tile[tx][ty + i]);
}

__global__ void x2half_kernel(const float* __restrict__ x, __half* __restrict__ xh)
{
    const int i = blockIdx.x * blockDim.x + threadIdx.x;
    if (i >= T_TOKENS * DIM / 4) return;
    const float4 v = ((const float4*)x)[i];
    const __half2 h0 = __floats2half2_rn(v.x, v.y);
    const __half2 h1 = __floats2half2_rn(v.z, v.w);
    uint2 u;
    u.x = *(const uint32_t*)&h0;
    u.y = *(const uint32_t*)&h1;
    ((uint2*)xh)[i] = u;
}

__global__ void zero_out_kernel(float* __restrict__ out)
{
    const int i = blockIdx.x * blockDim.x + threadIdx.x;
    if (i < T_TOKENS * DIM / 4)
        ((float4*)out)[i] = make_float4(0.f, 0.f, 0.f, 0.f);
}

__global__ void zero_cnt_kernel() {
    if (threadIdx.x < NEXP) g_cnt[threadIdx.x] = 0;
    if (threadIdx.x < 2)    g_ctr[threadIdx.x] = 0;
}

// offsets + cumulative row-tile table
__global__ void offsets_kernel() {
    if (threadIdx.x == 0) {
        int s = 0, rt = 0;
        for (int e = 0; e < NEXP; e++) {
            g_off[e] = s;
            g_rt[e] = rt;
            rt += (g_cnt[e] + 127) / 128;
            s += g_cnt[e];
        }
        g_rt[NEXP] = rt;
    }
}

__global__ void dispatch_meta_kernel()
{
    const int l = blockIdx.x * blockDim.x + threadIdx.x;
    if (l >= NSLOTS) return;
    int e = 0;
#pragma unroll
    for (int k = 1; k < NEXP; k++) if (l >= g_off[k]) e = k;
    const int p = l - g_off[e];
    const int t = g_tok[e * T_TOKENS + p];
    g_ptok[l] = t;
    g_pw[l] = g_rw[g_slot[e * T_TOKENS + p]];
}

// ---------------- host ----------------
extern "C" void kernel_launch(void* const* d_in, const int* in_sizes, int n_in,
                              void* d_out, int out_size)
{
    const float* x   = (const float*)d_in[0];
    const float* rw1 = (const float*)d_in[1];
    const float* rw2 = (const float*)d_in[2];
    const float* W1  = (const float*)d_in[3];
    const float* W2  = (const float*)d_in[4];
    float* out = (float*)d_out;

    void *xh, *hp, *w1t, *w2t, *rpart, *cntp, *offp, *ptokp, *pwp;
    cudaGetSymbolAddress(&xh, g_xh);
    cudaGetSymbolAddress(&hp, g_h);
    cudaGetSymbolAddress(&w1t, g_w1t);
    cudaGetSymbolAddress(&w2t, g_w2t);
    cudaGetSymbolAddress(&rpart, g_rpart);
    cudaGetSymbolAddress(&cntp, g_cnt);
    cudaGetSymbolAddress(&offp, g_off);
    cudaGetSymbolAddress(&ptokp, g_ptok);
    cudaGetSymbolAddress(&pwp, g_pw);

    int nsm = 148;
    cudaDeviceGetAttribute(&nsm, cudaDevAttrMultiProcessorCount, 0);
    const int PGRID = 2 * nsm;

    const int SMEM_H = HSTAGES * SBYT_H;   // 81920
    const int SMEM_R = RSTAGES * SBYT;     // 107520
    cudaFuncSetAttribute(hgemm<0>,
                         cudaFuncAttributeMaxDynamicSharedMemorySize, SMEM_H);
    cudaFuncSetAttribute(hgemm<1>,
                         cudaFuncAttributeMaxDynamicSharedMemorySize, SMEM_H);
    cudaFuncSetAttribute(router_mma,
                         cudaFuncAttributeMaxDynamicSharedMemorySize, SMEM_R);

    // side stream with dependency-matched split joins
    cudaStream_t s1;
    cudaStreamCreate(&s1);
    cudaEvent_t e0, e1, e2;
    cudaEventCreateWithFlags(&e0, cudaEventDisableTiming);
    cudaEventCreateWithFlags(&e1, cudaEventDisableTiming);
    cudaEventCreateWithFlags(&e2, cudaEventDisableTiming);

    // 1. zero counters (main); fork side stream
    zero_cnt_kernel<<<1, 32>>>();
    cudaEventRecord(e0, 0);
    cudaStreamWaitEvent(s1, e0, 0);

    // 2a. side stream, phase 1: GEMM1 prerequisites (W1^T + x->half)
    transpose_half_kernel<<<dim3(FF / 32, DIM / 32, NEXP), dim3(32, 8), 0, s1>>>(
        W1, (__half*)w1t, DIM, FF);
    x2half_kernel<<<(T_TOKENS * DIM / 4 + 255) / 256, 256, 0, s1>>>(x, (__half*)xh);
    cudaEventRecord(e1, s1);

    // 2b. side stream, phase 2: GEMM2 prerequisites (W2^T + out-zero)
    transpose_half_kernel<<<dim3(DIM / 32, FF / 32, NEXP), dim3(32, 8), 0, s1>>>(
        W2, (__half*)w2t, FF, DIM);
    zero_out_kernel<<<(T_TOKENS * DIM / 4 + 255) / 256, 256, 0, s1>>>(out);
    cudaEventRecord(e2, s1);

    // 3. router hidden partials (fp16x3 K-split MMA)
    router_mma<<<dim3(KSPLIT, T_TOKENS / 128), 256, SMEM_R>>>(x, rw1, (float*)rpart);

    // 4. fused reduce+silu+logits+top-2
    router_topk_kernel<<<T_TOKENS / 8, 256>>>((const float*)rpart, rw2);

    // 5. offsets + row-tile table + perm-row metadata
    offsets_kernel<<<1, 32>>>();
    dispatch_meta_kernel<<<(NSLOTS + 255) / 256, 256>>>();

    // join 1: GEMM1 prerequisites
    cudaStreamWaitEvent(0, e1, 0);

    // 6. persistent grouped GEMM1: h = silu(x[tok] @ W1[e])
    hgemm<0><<<PGRID, 256, SMEM_H>>>(
        (const __half*)xh, (const __half*)w1t, (__half*)hp, (float*)0,
        FF, DIM, (const int*)cntp, (const int*)offp,
        (const int*)ptokp, (const float*)pwp);

    // join 2: GEMM2 prerequisites
    cudaStreamWaitEvent(0, e2, 0);

    // 7. persistent grouped GEMM2: out[t] += w * (h @ W2[e])
    hgemm<1><<<PGRID, 256, SMEM_H>>>(
        (const __half*)hp, (const __half*)w2t, (__half*)0, out,
        DIM, FF, (const int*)cntp, (const int*)offp,
        (const int*)ptokp, (const float*)pwp);
}

// round 17
// speedup vs baseline: 1.0110x; 1.0110x over previous
#include <cuda_runtime.h>
#include <cuda_fp16.h>
#include <cstdint>

// ---------------- problem dims ----------------
#define T_TOKENS 8192
#define DIM      1024
#define FF       2048
#define NEXP     8
#define RH       128
#define NSLOTS   (T_TOKENS * 2)
#define KSPLIT   4

// ---------------- device scratch ----------------
__device__ __half g_xh[(long long)T_TOKENS * DIM];
__device__ __half g_h[(long long)NSLOTS * FF];
__device__ __half g_w1t[(long long)NEXP * FF * DIM];        // W1^T [e][f][d]
__device__ __half g_w2t[(long long)NEXP * DIM * FF];        // W2^T [e][d][f]
__device__ float  g_rpart[(long long)KSPLIT * T_TOKENS * RH];
__device__ int    g_tok[NEXP * T_TOKENS];
__device__ int    g_slot[NEXP * T_TOKENS];
__device__ int    g_cnt[NEXP];
__device__ int    g_ptok[NSLOTS];
__device__ float  g_pw[NSLOTS];
__device__ float  g_rw[NSLOTS];

// ---------------- helpers ----------------
__device__ __forceinline__ uint32_t cvta_s(const void* p) {
    uint32_t a;
    asm("{ .reg .u64 t; cvta.to.shared.u64 t, %1; cvt.u32.u64 %0, t; }" : "=r"(a) : "l"(p));
    return a;
}
__device__ __forceinline__ void cp16(uint32_t s, const void* g) {
    asm volatile("cp.async.cg.shared.global [%0], [%1], 16;" :: "r"(s), "l"(g));
}
__device__ __forceinline__ float silu_f(float v) { return v / (1.0f + __expf(-v)); }

__device__ __forceinline__ void mma16816(float* c, const uint32_t* a, const uint32_t* b) {
    asm volatile(
        "mma.sync.aligned.m16n8k16.row.col.f32.f16.f16.f32 "
        "{%0,%1,%2,%3}, {%4,%5,%6,%7}, {%8,%9}, {%0,%1,%2,%3};"
        : "+f"(c[0]), "+f"(c[1]), "+f"(c[2]), "+f"(c[3])
        : "r"(a[0]), "r"(a[1]), "r"(a[2]), "r"(a[3]), "r"(b[0]), "r"(b[1]));
}

__device__ __forceinline__ void splitpair(float x, float y, uint32_t& hi, uint32_t& lo) {
    const __half2 h = __floats2half2_rn(x, y);
    const float2 hf = __half22float2(h);
    const __half2 l = __floats2half2_rn(x - hf.x, y - hf.y);
    hi = *(const uint32_t*)&h;
    lo = *(const uint32_t*)&l;
}

// ================ fp16 grouped GEMM (m16n8k16) ================
// MODE 0: A rows gathered via ptok from g_xh; silu -> half out (perm rows).
// MODE 1: A rows direct (perm order); weighted atomicAdd into out[token].
//         Exactly 2 contributions per element -> commutative fp32 add ->
//         bit-deterministic.
#define HSTAGES 4
#define ASTR_H  40
#define A_HALFS (128 * ASTR_H)
#define B_HALFS (128 * ASTR_H)
#define SFH     (A_HALFS + B_HALFS)
#define SBYT_H  (SFH * 2)

template <int MODE>
__global__ __launch_bounds__(256, 2)
void hgemm(const __half* __restrict__ A, const __half* __restrict__ Bt,
           __half* __restrict__ Ch, float* __restrict__ Cf,
           int N, int K,
           const int* __restrict__ cnt,
           const int* __restrict__ ptok, const float* __restrict__ pw)
{
    extern __shared__ __half smh[];
    const int e = blockIdx.z;
    // inline prefix over 8 counters (replaces offsets_kernel)
    int o = 0;
#pragma unroll
    for (int k = 0; k < NEXP; k++) { const int ck = cnt[k]; if (k < e) o += ck; }
    const int c = cnt[e];
    if ((int)blockIdx.y * 128 >= c) return;
    const int row0 = o + blockIdx.y * 128;
    const int mend = o + c;
    const int n0 = blockIdx.x * 128;
    const __half* Bp = Bt + (long long)e * N * K;

    const int tid = threadIdx.x;
    const uint32_t sbase = cvta_s(smh);

    const __half* aSrc[2]; uint32_t aDst[2];
    const __half* bSrc[2]; uint32_t bDst[2];
#pragma unroll
    for (int i = 0; i < 2; i++) {
        const int idx = tid + i * 256;
        const int ar = idx >> 2, ac = idx & 3;
        int prow = row0 + ar;
        if (prow > mend - 1) prow = mend - 1;
        const long long arow = (MODE == 0) ? (long long)ptok[prow] : (long long)prow;
        aSrc[i] = A + arow * K + ac * 8;
        aDst[i] = sbase + (uint32_t)(ar * 80 + ac * 16);
        bSrc[i] = Bp + (long long)(n0 + ar) * K + ac * 8;
        bDst[i] = sbase + (uint32_t)(A_HALFS * 2 + ar * 80 + ac * 16);
    }

    const int nk = K / 32;
#pragma unroll
    for (int s = 0; s < 3; s++) {
#pragma unroll
        for (int i = 0; i < 2; i++) {
            cp16(aDst[i] + s * SBYT_H, aSrc[i] + s * 32);
            cp16(bDst[i] + s * SBYT_H, bSrc[i] + s * 32);
        }
        asm volatile("cp.async.commit_group;" ::: "memory");
    }

    const int wid = tid >> 5, lane = tid & 31;
    const int wm = (wid & 3) * 32, wn = (wid >> 2) * 64;
    const int l4 = lane >> 2, lq = lane & 3;

    float acc[2][8][4];
#pragma unroll
    for (int mt = 0; mt < 2; mt++)
#pragma unroll
        for (int nt = 0; nt < 8; nt++)
#pragma unroll
            for (int q = 0; q < 4; q++) acc[mt][nt][q] = 0.0f;

    for (int kt = 0; kt < nk; kt++) {
        asm volatile("cp.async.wait_group 2;" ::: "memory");
        __syncthreads();
        if (kt + 3 < nk) {
            const int s = (kt + 3) & 3;
#pragma unroll
            for (int i = 0; i < 2; i++) {
                cp16(aDst[i] + s * SBYT_H, aSrc[i] + (kt + 3) * 32);
                cp16(bDst[i] + s * SBYT_H, bSrc[i] + (kt + 3) * 32);
            }
        }
        asm volatile("cp.async.commit_group;" ::: "memory");

        const __half* st = smh + (kt & 3) * SFH;
#pragma unroll
        for (int ks = 0; ks < 2; ks++) {
            const int kk = ks * 16;
            uint32_t a[2][4], b[8][2];
#pragma unroll
            for (int mt = 0; mt < 2; mt++) {
                const __half* ap = st + (wm + mt * 16 + l4) * ASTR_H + kk + 2 * lq;
                a[mt][0] = *(const uint32_t*)(ap);
                a[mt][1] = *(const uint32_t*)(ap + 8 * ASTR_H);
                a[mt][2] = *(const uint32_t*)(ap + 8);
                a[mt][3] = *(const uint32_t*)(ap + 8 * ASTR_H + 8);
            }
#pragma unroll
            for (int nt = 0; nt < 8; nt++) {
                const __half* bp = st + A_HALFS + (wn + nt * 8 + l4) * ASTR_H + kk + 2 * lq;
                b[nt][0] = *(const uint32_t*)(bp);
                b[nt][1] = *(const uint32_t*)(bp + 8);
            }
#pragma unroll
            for (int mt = 0; mt < 2; mt++)
#pragma unroll
                for (int nt = 0; nt < 8; nt++)
                    mma16816(acc[mt][nt], a[mt], b[nt]);
        }
    }

    // epilogue
#pragma unroll
    for (int mt = 0; mt < 2; mt++) {
#pragma unroll
        for (int hr = 0; hr < 2; hr++) {
            const int row = row0 + wm + mt * 16 + l4 + hr * 8;
            if (row < mend) {
                if (MODE == 0) {
                    __half* cp0 = Ch + (long long)row * N + n0 + wn + lq * 2;
#pragma unroll
                    for (int nt = 0; nt < 8; nt++) {
                        const float v0 = silu_f(acc[mt][nt][hr * 2 + 0]);
                        const float v1 = silu_f(acc[mt][nt][hr * 2 + 1]);
                        *(__half2*)(cp0 + nt * 8) = __floats2half2_rn(v0, v1);
                    }
                } else {
                    const int t = ptok[row];
                    const float w = pw[row];
                    float* cp0 = Cf + (long long)t * N + n0 + wn + lq * 2;
#pragma unroll
                    for (int nt = 0; nt < 8; nt++) {
                        atomicAdd(cp0 + nt * 8 + 0, w * acc[mt][nt][hr * 2 + 0]);
                        atomicAdd(cp0 + nt * 8 + 1, w * acc[mt][nt][hr * 2 + 1]);
                    }
                }
            }
        }
    }
}

// ================ router hidden: fp16x3 MMA with K-split ================
#define RSTAGES 3
#define ASTR 36
#define BSTR 136
#define AFL  (128 * ASTR)
#define BFL  (32 * BSTR)
#define SF   (AFL + BFL)
#define SBYT (SF * 4)

__global__ __launch_bounds__(256, 2)   // cap regs at 128 -> 2 CTA/SM -> 1 wave
void router_mma(const float* __restrict__ x, const float* __restrict__ rw1,
                float* __restrict__ part)
{
    extern __shared__ float sm[];
    const int kz = blockIdx.x;
    const int row0 = blockIdx.y * 128;
    const int kbase = kz * (DIM / KSPLIT);

    const int tid = threadIdx.x;
    const uint32_t sbase = cvta_s(sm);

    const float* aSrc[4]; uint32_t aDst[4];
    const float* bSrc[4]; uint32_t bDst[4];
#pragma unroll
    for (int i = 0; i < 4; i++) {
        const int cidx = tid + i * 256;
        const int ar = cidx >> 3, ak = (cidx & 7) * 4;
        aSrc[i] = x + (long long)(row0 + ar) * DIM + kbase + ak;
        aDst[i] = sbase + (uint32_t)(ar * ASTR + ak) * 4u;
        const int bk = cidx >> 5, bn = (cidx & 31) * 4;
        bSrc[i] = rw1 + (long long)(kbase + bk) * RH + bn;
        bDst[i] = sbase + (uint32_t)(AFL + bk * BSTR + bn) * 4u;
    }

    const int nk = (DIM / KSPLIT) / 32;
#pragma unroll
    for (int s = 0; s < 2; s++) {
#pragma unroll
        for (int i = 0; i < 4; i++) {
            cp16(aDst[i] + s * SBYT, aSrc[i] + s * 32);
            cp16(bDst[i] + s * SBYT, bSrc[i] + (long long)s * 32 * RH);
        }
        asm volatile("cp.async.commit_group;" ::: "memory");
    }

    const int wid = tid >> 5, lane = tid & 31;
    const int wm = (wid & 3) * 32, wn = (wid >> 2) * 64;
    const int l4 = lane >> 2, lq = lane & 3;

    float acc[2][8][4];
#pragma unroll
    for (int mt = 0; mt < 2; mt++)
#pragma unroll
        for (int nt = 0; nt < 8; nt++)
#pragma unroll
            for (int q = 0; q < 4; q++) acc[mt][nt][q] = 0.0f;

    int rstage = 0, pstage = 2;
    for (int kt = 0; kt < nk; kt++) {
        asm volatile("cp.async.wait_group 1;" ::: "memory");
        __syncthreads();
        if (kt + 2 < nk) {
#pragma unroll
            for (int i = 0; i < 4; i++) {
                cp16(aDst[i] + pstage * SBYT, aSrc[i] + (kt + 2) * 32);
                cp16(bDst[i] + pstage * SBYT, bSrc[i] + (long long)(kt + 2) * 32 * RH);
            }
        }
        asm volatile("cp.async.commit_group;" ::: "memory");

        const float* st = sm + rstage * SF;
#pragma unroll
        for (int ks = 0; ks < 2; ks++) {
            const int kk = ks * 16;
            uint32_t ah[2][4], al[2][4], bh[8][2], bl[8][2];
#pragma unroll
            for (int mt = 0; mt < 2; mt++) {
                const float* ap = st + (wm + mt * 16 + l4) * ASTR + kk + 2 * lq;
                splitpair(ap[0],              ap[1],              ah[mt][0], al[mt][0]);
                splitpair(ap[8 * ASTR],       ap[8 * ASTR + 1],   ah[mt][1], al[mt][1]);
                splitpair(ap[8],              ap[9],              ah[mt][2], al[mt][2]);
                splitpair(ap[8 * ASTR + 8],   ap[8 * ASTR + 9],   ah[mt][3], al[mt][3]);
            }
#pragma unroll
            for (int nt = 0; nt < 8; nt++) {
                const float* bp = st + AFL + (kk + 2 * lq) * BSTR + wn + nt * 8 + l4;
                splitpair(bp[0],        bp[BSTR],     bh[nt][0], bl[nt][0]);
                splitpair(bp[8 * BSTR], bp[9 * BSTR], bh[nt][1], bl[nt][1]);
            }
#pragma unroll
            for (int mt = 0; mt < 2; mt++)
#pragma unroll
                for (int nt = 0; nt < 8; nt++) {
                    mma16816(acc[mt][nt], ah[mt], bh[nt]);
                    mma16816(acc[mt][nt], ah[mt], bl[nt]);
                    mma16816(acc[mt][nt], al[mt], bh[nt]);
                }
        }
        if (++rstage == RSTAGES) rstage = 0;
        if (++pstage == RSTAGES) pstage = 0;
    }

    float* base = part + (long long)kz * T_TOKENS * RH;
#pragma unroll
    for (int mt = 0; mt < 2; mt++) {
#pragma unroll
        for (int hr = 0; hr < 2; hr++) {
            const int row = row0 + wm + mt * 16 + l4 + hr * 8;
            float* cp0 = base + (long long)row * RH + wn + lq * 2;
#pragma unroll
            for (int nt = 0; nt < 8; nt++) {
                float2 v;
                v.x = acc[mt][nt][hr * 2 + 0];
                v.y = acc[mt][nt][hr * 2 + 1];
                *(float2*)(cp0 + nt * 8) = v;
            }
        }
    }
}

// ---------------- fused: KSPLIT-reduce + silu + logits + top-2 ----------------
__global__ void router_topk_kernel(const float* __restrict__ part,
                                   const float* __restrict__ w2)
{
    const int warp = (blockIdx.x * blockDim.x + threadIdx.x) >> 5;
    const int lane = threadIdx.x & 31;
    if (warp >= T_TOKENS) return;
    const long long stride = (long long)T_TOKENS * RH;
    const long long base = (long long)warp * RH;

    float acc[NEXP];
#pragma unroll
    for (int e = 0; e < NEXP; e++) acc[e] = 0.0f;
#pragma unroll
    for (int j4 = 0; j4 < RH / 32; j4++) {
        const int j = j4 * 32 + lane;
        float s = part[base + j];
#pragma unroll
        for (int kz = 1; kz < KSPLIT; kz++) s += part[base + j + kz * stride];
        s = silu_f(s);
#pragma unroll
        for (int e = 0; e < NEXP; e++) acc[e] += s * w2[j * NEXP + e];
    }
#pragma unroll
    for (int off = 16; off > 0; off >>= 1)
#pragma unroll
        for (int e = 0; e < NEXP; e++)
            acc[e] += __shfl_xor_sync(0xffffffffu, acc[e], off);
    if (lane == 0) {
        float mx = acc[0];
#pragma unroll
        for (int e = 1; e < NEXP; e++) mx = fmaxf(mx, acc[e]);
        float p[NEXP];
#pragma unroll
        for (int e = 0; e < NEXP; e++) p[e] = __expf(acc[e] - mx);
        int i0 = 0;
#pragma unroll
        for (int e = 1; e < NEXP; e++) if (p[e] > p[i0]) i0 = e;
        int i1 = (i0 == 0) ? 1 : 0;
#pragma unroll
        for (int e = 0; e < NEXP; e++) if (e != i0 && p[e] > p[i1]) i1 = e;
        const float s = p[i0] + p[i1];
        const int t = warp;
        int pos0 = atomicAdd(&g_cnt[i0], 1);
        g_tok[i0 * T_TOKENS + pos0]  = t;
        g_slot[i0 * T_TOKENS + pos0] = 2 * t;
        g_rw[2 * t] = p[i0] / s;
        int pos1 = atomicAdd(&g_cnt[i1], 1);
        g_tok[i1 * T_TOKENS + pos1]  = t;
        g_slot[i1 * T_TOKENS + pos1] = 2 * t + 1;
        g_rw[2 * t + 1] = p[i1] / s;
    }
}

// ---------------- conversions ----------------
__global__ void transpose_half_kernel(const float* __restrict__ src,
                                      __half* __restrict__ dst, int R, int C)
{
    __shared__ float tile[32][33];
    const int e = blockIdx.z;
    const float* s = src + (long long)e * R * C;
    __half* d = dst + (long long)e * R * C;
    const int c0 = blockIdx.x * 32, r0 = blockIdx.y * 32;
    const int tx = threadIdx.x, ty = threadIdx.y;
#pragma unroll
    for (int i = 0; i < 32; i += 8)
        tile[ty + i][tx] = s[(long long)(r0 + ty + i) * C + c0 + tx];
    __syncthreads();
#pragma unroll
    for (int i = 0; i < 32; i += 8)
        d[(long long)(c0 + ty + i) * R + r0 + tx] = __float2half_rn(tile[tx][ty + i]);
}

__global__ void x2half_kernel(const float* __restrict__ x, __half* __restrict__ xh)
{
    const int i = blockIdx.x * blockDim.x + threadIdx.x;
    if (i >= T_TOKENS * DIM / 4) return;
    const float4 v = ((const float4*)x)[i];
    const __half2 h0 = __floats2half2_rn(v.x, v.y);
    const __half2 h1 = __floats2half2_rn(v.z, v.w);
    uint2 u;
    u.x = *(const uint32_t*)&h0;
    u.y = *(const uint32_t*)&h1;
    ((uint2*)xh)[i] = u;
}

__global__ void zero_out_kernel(float* __restrict__ out)
{
    const int i = blockIdx.x * blockDim.x + threadIdx.x;
    if (i < T_TOKENS * DIM / 4)
        ((float4*)out)[i] = make_float4(0.f, 0.f, 0.f, 0.f);
}

__global__ void zero_cnt_kernel() { if (threadIdx.x < NEXP) g_cnt[threadIdx.x] = 0; }

// perm-row metadata; offsets computed inline from g_cnt (8-prefix)
__global__ void dispatch_meta_kernel()
{
    const int l = blockIdx.x * blockDim.x + threadIdx.x;
    if (l >= NSLOTS) return;
    int offv[NEXP];
    int s = 0;
#pragma unroll
    for (int k = 0; k < NEXP; k++) { offv[k] = s; s += g_cnt[k]; }
    int e = 0;
#pragma unroll
    for (int k = 1; k < NEXP; k++) if (l >= offv[k]) e = k;
    const int p = l - offv[e];
    const int t = g_tok[e * T_TOKENS + p];
    g_ptok[l] = t;
    g_pw[l] = g_rw[g_slot[e * T_TOKENS + p]];
}

// ---------------- host ----------------
extern "C" void kernel_launch(void* const* d_in, const int* in_sizes, int n_in,
                              void* d_out, int out_size)
{
    const float* x   = (const float*)d_in[0];
    const float* rw1 = (const float*)d_in[1];
    const float* rw2 = (const float*)d_in[2];
    const float* W1  = (const float*)d_in[3];
    const float* W2  = (const float*)d_in[4];
    float* out = (float*)d_out;

    void *xh, *hp, *w1t, *w2t, *rpart, *cntp, *ptokp, *pwp;
    cudaGetSymbolAddress(&xh, g_xh);
    cudaGetSymbolAddress(&hp, g_h);
    cudaGetSymbolAddress(&w1t, g_w1t);
    cudaGetSymbolAddress(&w2t, g_w2t);
    cudaGetSymbolAddress(&rpart, g_rpart);
    cudaGetSymbolAddress(&cntp, g_cnt);
    cudaGetSymbolAddress(&ptokp, g_ptok);
    cudaGetSymbolAddress(&pwp, g_pw);

    const int SMEM_H = HSTAGES * SBYT_H;   // 81920
    const int SMEM_R = RSTAGES * SBYT;     // 107520
    cudaFuncSetAttribute(hgemm<0>,
                         cudaFuncAttributeMaxDynamicSharedMemorySize, SMEM_H);
    cudaFuncSetAttribute(hgemm<1>,
                         cudaFuncAttributeMaxDynamicSharedMemorySize, SMEM_H);
    cudaFuncSetAttribute(router_mma,
                         cudaFuncAttributeMaxDynamicSharedMemorySize, SMEM_R);

    // side stream with dependency-matched split joins
    cudaStream_t s1;
    cudaStreamCreate(&s1);
    cudaEvent_t e0, e1, e2;
    cudaEventCreateWithFlags(&e0, cudaEventDisableTiming);
    cudaEventCreateWithFlags(&e1, cudaEventDisableTiming);
    cudaEventCreateWithFlags(&e2, cudaEventDisableTiming);

    // 1. zero counters (main); fork side stream
    zero_cnt_kernel<<<1, 32>>>();
    cudaEventRecord(e0, 0);
    cudaStreamWaitEvent(s1, e0, 0);

    // 2a. side stream, phase 1: GEMM1 prerequisites (W1^T + x->half)
    transpose_half_kernel<<<dim3(FF / 32, DIM / 32, NEXP), dim3(32, 8), 0, s1>>>(
        W1, (__half*)w1t, DIM, FF);
    x2half_kernel<<<(T_TOKENS * DIM / 4 + 255) / 256, 256, 0, s1>>>(x, (__half*)xh);
    cudaEventRecord(e1, s1);

    // 2b. side stream, phase 2: GEMM2 prerequisites (W2^T + out-zero)
    transpose_half_kernel<<<dim3(DIM / 32, FF / 32, NEXP), dim3(32, 8), 0, s1>>>(
        W2, (__half*)w2t, FF, DIM);
    zero_out_kernel<<<(T_TOKENS * DIM / 4 + 255) / 256, 256, 0, s1>>>(out);
    cudaEventRecord(e2, s1);

    // 3. router hidden partials (fp16x3 K-split MMA, 2 CTA/SM single wave)
    router_mma<<<dim3(KSPLIT, T_TOKENS / 128), 256, SMEM_R>>>(x, rw1, (float*)rpart);

    // 4. fused reduce+silu+logits+top-2
    router_topk_kernel<<<T_TOKENS / 8, 256>>>((const float*)rpart, rw2);

    // 5. perm-row metadata (offsets computed inline)
    dispatch_meta_kernel<<<(NSLOTS + 255) / 256, 256>>>();

    // join 1: GEMM1 prerequisites
    cudaStreamWaitEvent(0, e1, 0);

    // 6. grouped GEMM1 (gather-A): h = silu(x[tok] @ W1[e])
    hgemm<0><<<dim3(FF / 128, T_TOKENS / 128, NEXP), 256, SMEM_H>>>(
        (const __half*)xh, (const __half*)w1t, (__half*)hp, (float*)0,
        FF, DIM, (const int*)cntp,
        (const int*)ptokp, (const float*)pwp);

    // join 2: GEMM2 prerequisites
    cudaStreamWaitEvent(0, e2, 0);

    // 7. grouped GEMM2 (weighted atomic scatter): out[t] += w * (h @ W2[e])
    hgemm<1><<<dim3(DIM / 128, T_TOKENS / 128, NEXP), 256, SMEM_H>>>(
        (const __half*)hp, (const __half*)w2t, (__half*)0, out,
        DIM, FF, (const int*)cntp,
        (const int*)ptokp, (const float*)pwp);
}